// round 4
// baseline (speedup 1.0000x reference)
#include <cuda_runtime.h>
#include <cstdint>

// ============================================================================
// SensorCalibration: 450 Adam steps on 17 independent axis-angle rotations.
// Exact gradient depends on data only via M[j,k,i,l] = sum_t A[j,k] B[i,l].
// Threefry core KAT-verified; gradient formula verified on analytic cases.
// RNG: JAX partitionable path, bit_width=32 branch returns bits1 ^ bits2
// (jax/_src/prng.py _threefry_random_bits_partitionable).
//   R1 original pad/split path (o0/o1 halves) -> 0.726
//   R2 low word o1                            -> 0.693
//   R3 high word o0                           -> 0.569
//   R4 o0 ^ o1                                <- this round
// ============================================================================

#define NSENS 17
#define NT    16384
#define ROWLEN (NSENS * 9)
#define NBLK  8

__device__ float gPart[NSENS][NBLK][81];

// ---------------------------------------------------------------------------
// Kernel 1: per-block partials of M[n][jk][il] = sum_t org[t,n,jk]*trg[t,n,il]
// ---------------------------------------------------------------------------
__global__ void reduce_kernel(const float* __restrict__ org,
                              const float* __restrict__ trg) {
    const int n    = blockIdx.y;
    const int base = blockIdx.x * blockDim.x + threadIdx.x;   // 0..2047

    float acc[81];
#pragma unroll
    for (int i = 0; i < 81; i++) acc[i] = 0.0f;

#pragma unroll
    for (int kk = 0; kk < 8; kk++) {
        const int t = base + kk * 2048;
        const float* a = org + (size_t)t * ROWLEN + n * 9;
        const float* b = trg + (size_t)t * ROWLEN + n * 9;
        float av[9], bv[9];
#pragma unroll
        for (int i = 0; i < 9; i++) { av[i] = a[i]; bv[i] = b[i]; }
#pragma unroll
        for (int jk = 0; jk < 9; jk++)
#pragma unroll
            for (int il = 0; il < 9; il++)
                acc[jk * 9 + il] = fmaf(av[jk], bv[il], acc[jk * 9 + il]);
    }

    const int lane = threadIdx.x & 31;
    const int wid  = threadIdx.x >> 5;
    __shared__ float sW[8][81];
#pragma unroll
    for (int e = 0; e < 81; e++) {
        float p = acc[e];
        p += __shfl_xor_sync(0xFFFFFFFFu, p, 16);
        p += __shfl_xor_sync(0xFFFFFFFFu, p, 8);
        p += __shfl_xor_sync(0xFFFFFFFFu, p, 4);
        p += __shfl_xor_sync(0xFFFFFFFFu, p, 2);
        p += __shfl_xor_sync(0xFFFFFFFFu, p, 1);
        if (lane == 0) sW[wid][e] = p;
    }
    __syncthreads();
    if (threadIdx.x < 81) {
        float s = 0.0f;
#pragma unroll
        for (int w = 0; w < 8; w++) s += sW[w][threadIdx.x];
        gPart[n][blockIdx.x][threadIdx.x] = s;
    }
}

// ---------------------------------------------------------------------------
// Threefry2x32-20, key (0,1).  Core verified against Random123 KAT.
// ---------------------------------------------------------------------------
__device__ __forceinline__ uint32_t rotl32(uint32_t v, uint32_t d) {
    return (v << d) | (v >> (32u - d));
}

__device__ void threefry_01(uint32_t x0, uint32_t x1, uint32_t& o0, uint32_t& o1) {
    const uint32_t k0 = 0u, k1 = 1u;
    const uint32_t k2 = k0 ^ k1 ^ 0x1BD11BDAu;
    x0 += k0; x1 += k1;
    x0 += x1; x1 = rotl32(x1, 13); x1 ^= x0;
    x0 += x1; x1 = rotl32(x1, 15); x1 ^= x0;
    x0 += x1; x1 = rotl32(x1, 26); x1 ^= x0;
    x0 += x1; x1 = rotl32(x1,  6); x1 ^= x0;
    x0 += k1; x1 += k2 + 1u;
    x0 += x1; x1 = rotl32(x1, 17); x1 ^= x0;
    x0 += x1; x1 = rotl32(x1, 29); x1 ^= x0;
    x0 += x1; x1 = rotl32(x1, 16); x1 ^= x0;
    x0 += x1; x1 = rotl32(x1, 24); x1 ^= x0;
    x0 += k2; x1 += k0 + 2u;
    x0 += x1; x1 = rotl32(x1, 13); x1 ^= x0;
    x0 += x1; x1 = rotl32(x1, 15); x1 ^= x0;
    x0 += x1; x1 = rotl32(x1, 26); x1 ^= x0;
    x0 += x1; x1 = rotl32(x1,  6); x1 ^= x0;
    x0 += k0; x1 += k1 + 3u;
    x0 += x1; x1 = rotl32(x1, 17); x1 ^= x0;
    x0 += x1; x1 = rotl32(x1, 29); x1 ^= x0;
    x0 += x1; x1 = rotl32(x1, 16); x1 ^= x0;
    x0 += x1; x1 = rotl32(x1, 24); x1 ^= x0;
    x0 += k1; x1 += k2 + 4u;
    x0 += x1; x1 = rotl32(x1, 13); x1 ^= x0;
    x0 += x1; x1 = rotl32(x1, 15); x1 ^= x0;
    x0 += x1; x1 = rotl32(x1, 26); x1 ^= x0;
    x0 += x1; x1 = rotl32(x1,  6); x1 ^= x0;
    x0 += k2; x1 += k0 + 5u;
    o0 = x0; o1 = x1;
}

__device__ float ang_init(int f) {   // flat index 0..50
    uint32_t o0, o1;
    threefry_01(0u, (uint32_t)f, o0, o1);
    uint32_t bits = o0 ^ o1;         // <-- THIS ROUND: xor of output words
    uint32_t fb = (bits >> 9) | 0x3F800000u;
    return __uint_as_float(fb) - 1.0f;
}

// ---------------------------------------------------------------------------
// Kernel 2: 450 Adam iterations, one thread per sensor.
// ---------------------------------------------------------------------------
__global__ void __launch_bounds__(32, 1) adam_kernel(float* __restrict__ out) {
    const int n = threadIdx.x;
    if (n >= NSENS) return;

    double Md[81];
#pragma unroll
    for (int e = 0; e < 81; e++) {
        double s = 0.0;
#pragma unroll
        for (int b = 0; b < NBLK; b++) s += (double)gPart[n][b][e];
        Md[e] = s;
    }

    float Ms[81];
#pragma unroll
    for (int p = 0; p < 3; p++)
#pragma unroll
        for (int k = 0; k < 3; k++)
#pragma unroll
            for (int q = 0; q < 3; q++)
#pragma unroll
                for (int l = 0; l < 3; l++)
                    Ms[((p * 3 + k) * 3 + q) * 3 + l] =
                        (float)(Md[(3 * p + k) * 9 + 3 * q + l] +
                                Md[(3 * k + p) * 9 + 3 * l + q]);

    float rx = ang_init(3 * n + 0);
    float ry = ang_init(3 * n + 1);
    float rz = ang_init(3 * n + 2);
    float mx = 0.f, my = 0.f, mz = 0.f;
    float vx = 0.f, vy = 0.f, vz = 0.f;
    double pw1 = 1.0, pw2 = 1.0;

    const float lw2 = 2.0f * 10.0f;

    for (int it = 0; it < 450; it++) {
        const float lr = (it < 150) ? 0.01f : ((it < 300) ? 0.009f : 0.0081f);

        float th2 = rx * rx + ry * ry + rz * rz;
        float th  = sqrtf(th2);
        float ths = fmaxf(th, 1e-12f);
        float inv = 1.0f / ths;
        float kx = rx * inv, ky = ry * inv, kz = rz * inv;
        float s, c;
        sincosf(th, &s, &c);
        float o = 1.0f - c;

        float C[3][3];
        C[0][0] = c + o * kx * kx;
        C[0][1] = -s * kz + o * kx * ky;
        C[0][2] =  s * ky + o * kx * kz;
        C[1][0] =  s * kz + o * ky * kx;
        C[1][1] = c + o * ky * ky;
        C[1][2] = -s * kx + o * ky * kz;
        C[2][0] = -s * ky + o * kz * kx;
        C[2][1] =  s * kx + o * kz * ky;
        C[2][2] = c + o * kz * kz;

        float D[3][3];
#pragma unroll
        for (int p = 0; p < 3; p++)
#pragma unroll
            for (int q = 0; q < 3; q++) {
                float acc = 0.0f;
#pragma unroll
                for (int k = 0; k < 3; k++)
#pragma unroll
                    for (int l = 0; l < 3; l++)
                        acc = fmaf(Ms[((p * 3 + k) * 3 + q) * 3 + l], C[k][l], acc);
                D[p][q] = acc;
            }

        float tD = D[0][0] + D[1][1] + D[2][2];
        float wx = D[2][1] - D[1][2];
        float wy = D[0][2] - D[2][0];
        float wz = D[1][0] - D[0][1];
        float kw = kx * wx + ky * wy + kz * wz;

        float Dkx = D[0][0] * kx + D[0][1] * ky + D[0][2] * kz;
        float Dky = D[1][0] * kx + D[1][1] * ky + D[1][2] * kz;
        float Dkz = D[2][0] * kx + D[2][1] * ky + D[2][2] * kz;
        float DTkx = D[0][0] * kx + D[1][0] * ky + D[2][0] * kz;
        float DTky = D[0][1] * kx + D[1][1] * ky + D[2][1] * kz;
        float DTkz = D[0][2] * kx + D[1][2] * ky + D[2][2] * kz;
        float vxv = Dkx + DTkx, vyv = Dky + DTky, vzv = Dkz + DTkz;
        float q = kx * Dkx + ky * Dky + kz * Dkz;

        float si = s * inv;
        float oi = o * inv;
        float alpha = -s * tD + c * kw - si * kw + s * q - 2.0f * oi * q;

        float gx = -lw2 * (kx * alpha + si * wx + oi * vxv);
        float gy = -lw2 * (ky * alpha + si * wy + oi * vyv);
        float gz = -lw2 * (kz * alpha + si * wz + oi * vzv);

        mx = 0.9f * mx + 0.1f * gx;
        my = 0.9f * my + 0.1f * gy;
        mz = 0.9f * mz + 0.1f * gz;
        vx = 0.999f * vx + 0.001f * gx * gx;
        vy = 0.999f * vy + 0.001f * gy * gy;
        vz = 0.999f * vz + 0.001f * gz * gz;
        pw1 *= 0.9;  pw2 *= 0.999;
        float ib1 = 1.0f / (1.0f - (float)pw1);
        float ib2 = 1.0f / (1.0f - (float)pw2);

        rx -= lr * (mx * ib1) / (sqrtf(vx * ib2) + 1e-8f);
        ry -= lr * (my * ib1) / (sqrtf(vy * ib2) + 1e-8f);
        rz -= lr * (mz * ib1) / (sqrtf(vz * ib2) + 1e-8f);
    }

    out[3 * n + 0] = rx;
    out[3 * n + 1] = ry;
    out[3 * n + 2] = rz;
}

// ---------------------------------------------------------------------------
extern "C" void kernel_launch(void* const* d_in, const int* in_sizes, int n_in,
                              void* d_out, int out_size) {
    const float* org = (const float*)d_in[0];
    const float* trg = (const float*)d_in[1];
    float* out = (float*)d_out;

    reduce_kernel<<<dim3(NBLK, NSENS), 256>>>(org, trg);
    adam_kernel<<<1, 32>>>(out);
}

// round 5
// speedup vs baseline: 2.2559x; 2.2559x over previous
#include <cuda_runtime.h>
#include <cstdint>

// ============================================================================
// SensorCalibration: 450 Adam steps on 17 independent axis-angle rotations.
// Gradient depends on data only via M[j,k,i,l] = sum_t A[j,k] B[i,l].
// R4 passed (249.9us, rel_err 1.5e-4). R5: fast-math scalar adam kernel:
// MUFU approx trig/rsqrt/rcp/sqrt via PTX, f32 bias corrections, folded
// constants, S=D+D^T factorization. Target ~115-130us.
// ============================================================================

#define NSENS 17
#define NT    16384
#define ROWLEN (NSENS * 9)
#define NBLK  8

__device__ float gPart[NSENS][NBLK][81];

// ---------------------------------------------------------------------------
// fast approx intrinsics (force MUFU regardless of compile flags)
// ---------------------------------------------------------------------------
__device__ __forceinline__ float f_rsqrt(float x) { float r; asm("rsqrt.approx.f32 %0, %1;" : "=f"(r) : "f"(x)); return r; }
__device__ __forceinline__ float f_sin(float x)   { float r; asm("sin.approx.f32 %0, %1;"   : "=f"(r) : "f"(x)); return r; }
__device__ __forceinline__ float f_cos(float x)   { float r; asm("cos.approx.f32 %0, %1;"   : "=f"(r) : "f"(x)); return r; }
__device__ __forceinline__ float f_sqrt(float x)  { float r; asm("sqrt.approx.f32 %0, %1;"  : "=f"(r) : "f"(x)); return r; }
__device__ __forceinline__ float f_rcp(float x)   { float r; asm("rcp.approx.f32 %0, %1;"   : "=f"(r) : "f"(x)); return r; }

// ---------------------------------------------------------------------------
// Kernel 1: per-block partials of M[n][jk][il] = sum_t org[t,n,jk]*trg[t,n,il]
// ---------------------------------------------------------------------------
__global__ void reduce_kernel(const float* __restrict__ org,
                              const float* __restrict__ trg) {
    const int n    = blockIdx.y;
    const int base = blockIdx.x * blockDim.x + threadIdx.x;   // 0..2047

    float acc[81];
#pragma unroll
    for (int i = 0; i < 81; i++) acc[i] = 0.0f;

#pragma unroll
    for (int kk = 0; kk < 8; kk++) {
        const int t = base + kk * 2048;
        const float* a = org + (size_t)t * ROWLEN + n * 9;
        const float* b = trg + (size_t)t * ROWLEN + n * 9;
        float av[9], bv[9];
#pragma unroll
        for (int i = 0; i < 9; i++) { av[i] = a[i]; bv[i] = b[i]; }
#pragma unroll
        for (int jk = 0; jk < 9; jk++)
#pragma unroll
            for (int il = 0; il < 9; il++)
                acc[jk * 9 + il] = fmaf(av[jk], bv[il], acc[jk * 9 + il]);
    }

    const int lane = threadIdx.x & 31;
    const int wid  = threadIdx.x >> 5;
    __shared__ float sW[8][81];
#pragma unroll
    for (int e = 0; e < 81; e++) {
        float p = acc[e];
        p += __shfl_xor_sync(0xFFFFFFFFu, p, 16);
        p += __shfl_xor_sync(0xFFFFFFFFu, p, 8);
        p += __shfl_xor_sync(0xFFFFFFFFu, p, 4);
        p += __shfl_xor_sync(0xFFFFFFFFu, p, 2);
        p += __shfl_xor_sync(0xFFFFFFFFu, p, 1);
        if (lane == 0) sW[wid][e] = p;
    }
    __syncthreads();
    if (threadIdx.x < 81) {
        float s = 0.0f;
#pragma unroll
        for (int w = 0; w < 8; w++) s += sW[w][threadIdx.x];
        gPart[n][blockIdx.x][threadIdx.x] = s;
    }
}

// ---------------------------------------------------------------------------
// Threefry2x32-20, key (0,1), partitionable path: bits = o0 ^ o1.
// ---------------------------------------------------------------------------
__device__ __forceinline__ uint32_t rotl32(uint32_t v, uint32_t d) {
    return (v << d) | (v >> (32u - d));
}

__device__ void threefry_01(uint32_t x0, uint32_t x1, uint32_t& o0, uint32_t& o1) {
    const uint32_t k0 = 0u, k1 = 1u;
    const uint32_t k2 = k0 ^ k1 ^ 0x1BD11BDAu;
    x0 += k0; x1 += k1;
    x0 += x1; x1 = rotl32(x1, 13); x1 ^= x0;
    x0 += x1; x1 = rotl32(x1, 15); x1 ^= x0;
    x0 += x1; x1 = rotl32(x1, 26); x1 ^= x0;
    x0 += x1; x1 = rotl32(x1,  6); x1 ^= x0;
    x0 += k1; x1 += k2 + 1u;
    x0 += x1; x1 = rotl32(x1, 17); x1 ^= x0;
    x0 += x1; x1 = rotl32(x1, 29); x1 ^= x0;
    x0 += x1; x1 = rotl32(x1, 16); x1 ^= x0;
    x0 += x1; x1 = rotl32(x1, 24); x1 ^= x0;
    x0 += k2; x1 += k0 + 2u;
    x0 += x1; x1 = rotl32(x1, 13); x1 ^= x0;
    x0 += x1; x1 = rotl32(x1, 15); x1 ^= x0;
    x0 += x1; x1 = rotl32(x1, 26); x1 ^= x0;
    x0 += x1; x1 = rotl32(x1,  6); x1 ^= x0;
    x0 += k0; x1 += k1 + 3u;
    x0 += x1; x1 = rotl32(x1, 17); x1 ^= x0;
    x0 += x1; x1 = rotl32(x1, 29); x1 ^= x0;
    x0 += x1; x1 = rotl32(x1, 16); x1 ^= x0;
    x0 += x1; x1 = rotl32(x1, 24); x1 ^= x0;
    x0 += k1; x1 += k2 + 4u;
    x0 += x1; x1 = rotl32(x1, 13); x1 ^= x0;
    x0 += x1; x1 = rotl32(x1, 15); x1 ^= x0;
    x0 += x1; x1 = rotl32(x1, 26); x1 ^= x0;
    x0 += x1; x1 = rotl32(x1,  6); x1 ^= x0;
    x0 += k2; x1 += k0 + 5u;
    o0 = x0; o1 = x1;
}

__device__ float ang_init(int f) {
    uint32_t o0, o1;
    threefry_01(0u, (uint32_t)f, o0, o1);
    uint32_t bits = o0 ^ o1;
    uint32_t fb = (bits >> 9) | 0x3F800000u;
    return __uint_as_float(fb) - 1.0f;
}

// ---------------------------------------------------------------------------
// Kernel 2: 450 Adam iterations, one thread per sensor.
// Ms holds -2*lw * (M[p,k,q,l] + M[k,p,l,q]) so D is pre-scaled; gradient is
// g_a = k_a*alpha + si*w_a + oi*v_a with
//   alpha = -s*tD + (c-si)*kw + (s-2oi)*q,  S=D+D^T, v=S k, q=0.5*k.Sk
// ---------------------------------------------------------------------------
__global__ void __launch_bounds__(32, 1) adam_kernel(float* __restrict__ out) {
    const int n = threadIdx.x;
    if (n >= NSENS) return;

    double Md[81];
#pragma unroll
    for (int e = 0; e < 81; e++) {
        double s = 0.0;
#pragma unroll
        for (int b = 0; b < NBLK; b++) s += (double)gPart[n][b][e];
        Md[e] = s;
    }

    const float NEG_LW2 = -20.0f;   // -2 * lw
    float Ms[81];
#pragma unroll
    for (int p = 0; p < 3; p++)
#pragma unroll
        for (int k = 0; k < 3; k++)
#pragma unroll
            for (int q = 0; q < 3; q++)
#pragma unroll
                for (int l = 0; l < 3; l++)
                    Ms[((p * 3 + k) * 3 + q) * 3 + l] =
                        NEG_LW2 * (float)(Md[(3 * p + k) * 9 + 3 * q + l] +
                                          Md[(3 * k + p) * 9 + 3 * l + q]);

    float rx = ang_init(3 * n + 0);
    float ry = ang_init(3 * n + 1);
    float rz = ang_init(3 * n + 2);
    float mx = 0.f, my = 0.f, mz = 0.f;
    float vx = 0.f, vy = 0.f, vz = 0.f;
    float pw1 = 1.0f, pw2 = 1.0f;

    const float lr0 = 0.01f;
    const float lr1 = (float)(0.01 * 0.9);
    const float lr2 = (float)(0.01 * 0.9 * 0.9);

    for (int it = 0; it < 450; it++) {
        const float lr = (it < 150) ? lr0 : ((it < 300) ? lr1 : lr2);

        float th2 = fmaxf(rx * rx + ry * ry + rz * rz, 1e-24f);
        float inv = f_rsqrt(th2);
        float th  = th2 * inv;
        float kx = rx * inv, ky = ry * inv, kz = rz * inv;
        float s = f_sin(th);
        float c = f_cos(th);
        float o = 1.0f - c;

        float C[3][3];
        {
            float okx = o * kx, oky = o * ky, okz = o * kz;
            float skx = s * kx, sky = s * ky, skz = s * kz;
            C[0][0] = fmaf(okx, kx, c);
            C[0][1] = fmaf(okx, ky, -skz);
            C[0][2] = fmaf(okx, kz,  sky);
            C[1][0] = fmaf(oky, kx,  skz);
            C[1][1] = fmaf(oky, ky, c);
            C[1][2] = fmaf(oky, kz, -skx);
            C[2][0] = fmaf(okz, kx, -sky);
            C[2][1] = fmaf(okz, ky,  skx);
            C[2][2] = fmaf(okz, kz, c);
        }

        float D[3][3];
#pragma unroll
        for (int p = 0; p < 3; p++)
#pragma unroll
            for (int q = 0; q < 3; q++) {
                float acc = 0.0f;
#pragma unroll
                for (int k = 0; k < 3; k++)
#pragma unroll
                    for (int l = 0; l < 3; l++)
                        acc = fmaf(Ms[((p * 3 + k) * 3 + q) * 3 + l], C[k][l], acc);
                D[p][q] = acc;
            }

        float tD = D[0][0] + D[1][1] + D[2][2];
        float wx = D[2][1] - D[1][2];
        float wy = D[0][2] - D[2][0];
        float wz = D[1][0] - D[0][1];
        float kw = fmaf(kx, wx, fmaf(ky, wy, kz * wz));

        // S = D + D^T (off-diagonals), v = S k, q = 0.5 * k.Sk
        float s01 = D[0][1] + D[1][0];
        float s02 = D[0][2] + D[2][0];
        float s12 = D[1][2] + D[2][1];
        float d00 = D[0][0] + D[0][0];
        float d11 = D[1][1] + D[1][1];
        float d22 = D[2][2] + D[2][2];
        float vxv = fmaf(d00, kx, fmaf(s01, ky, s02 * kz));
        float vyv = fmaf(s01, kx, fmaf(d11, ky, s12 * kz));
        float vzv = fmaf(s02, kx, fmaf(s12, ky, d22 * kz));
        float q = 0.5f * fmaf(kx, vxv, fmaf(ky, vyv, kz * vzv));

        float si = s * inv;
        float oi = o * inv;
        float alpha = fmaf(-s, tD, fmaf(c - si, kw, (s - 2.0f * oi) * q));

        float gx = fmaf(kx, alpha, fmaf(si, wx, oi * vxv));
        float gy = fmaf(ky, alpha, fmaf(si, wy, oi * vyv));
        float gz = fmaf(kz, alpha, fmaf(si, wz, oi * vzv));

        mx = fmaf(0.9f, mx, 0.1f * gx);
        my = fmaf(0.9f, my, 0.1f * gy);
        mz = fmaf(0.9f, mz, 0.1f * gz);
        vx = fmaf(0.999f, vx, 0.001f * gx * gx);
        vy = fmaf(0.999f, vy, 0.001f * gy * gy);
        vz = fmaf(0.999f, vz, 0.001f * gz * gz);
        pw1 *= 0.9f;
        pw2 *= 0.999f;
        float c1 = lr * f_rcp(1.0f - pw1);          // lr / (1 - b1^t)
        float ib2 = f_rcp(1.0f - pw2);

        rx -= c1 * mx * f_rcp(f_sqrt(vx * ib2) + 1e-8f);
        ry -= c1 * my * f_rcp(f_sqrt(vy * ib2) + 1e-8f);
        rz -= c1 * mz * f_rcp(f_sqrt(vz * ib2) + 1e-8f);
    }

    out[3 * n + 0] = rx;
    out[3 * n + 1] = ry;
    out[3 * n + 2] = rz;
}

// ---------------------------------------------------------------------------
extern "C" void kernel_launch(void* const* d_in, const int* in_sizes, int n_in,
                              void* d_out, int out_size) {
    const float* org = (const float*)d_in[0];
    const float* trg = (const float*)d_in[1];
    float* out = (float*)d_out;

    reduce_kernel<<<dim3(NBLK, NSENS), 256>>>(org, trg);
    adam_kernel<<<1, 32>>>(out);
}

// round 6
// speedup vs baseline: 2.4270x; 1.0758x over previous
#include <cuda_runtime.h>
#include <cstdint>

// ============================================================================
// SensorCalibration. R6: packed f32x2 contraction of the 10 needed linear
// functionals (tD, w, S entries) instead of full D; smem table for Adam bias
// corrections; rsqrt-only Adam tail. R5 was 110.8us (adam 97.7).
// ============================================================================

#define NSENS 17
#define NT    16384
#define ROWLEN (NSENS * 9)
#define NBLK  8
#define NITER 450

__device__ float gPart[NSENS][NBLK][81];

// ---------------------------------------------------------------------------
// fast approx + packed f32x2 intrinsics
// ---------------------------------------------------------------------------
__device__ __forceinline__ float f_rsqrt(float x) { float r; asm("rsqrt.approx.f32 %0, %1;" : "=f"(r) : "f"(x)); return r; }
__device__ __forceinline__ float f_sin(float x)   { float r; asm("sin.approx.f32 %0, %1;"   : "=f"(r) : "f"(x)); return r; }
__device__ __forceinline__ float f_cos(float x)   { float r; asm("cos.approx.f32 %0, %1;"   : "=f"(r) : "f"(x)); return r; }
__device__ __forceinline__ float f_rcp(float x)   { float r; asm("rcp.approx.f32 %0, %1;"   : "=f"(r) : "f"(x)); return r; }
__device__ __forceinline__ float f_ex2(float x)   { float r; asm("ex2.approx.f32 %0, %1;"   : "=f"(r) : "f"(x)); return r; }

typedef unsigned long long u64;
__device__ __forceinline__ u64 pk2(float lo, float hi) {
    u64 r; asm("mov.b64 %0, {%1, %2};" : "=l"(r) : "f"(lo), "f"(hi)); return r;
}
__device__ __forceinline__ void upk2(float& lo, float& hi, u64 v) {
    asm("mov.b64 {%0, %1}, %2;" : "=f"(lo), "=f"(hi) : "l"(v));
}
__device__ __forceinline__ u64 fma2(u64 a, u64 b, u64 c) {
    u64 d; asm("fma.rn.f32x2 %0, %1, %2, %3;" : "=l"(d) : "l"(a), "l"(b), "l"(c)); return d;
}
__device__ __forceinline__ u64 mul2(u64 a, u64 b) {
    u64 d; asm("mul.rn.f32x2 %0, %1, %2;" : "=l"(d) : "l"(a), "l"(b)); return d;
}

// ---------------------------------------------------------------------------
// Kernel 1: per-block partials of M[n][jk][il] = sum_t org[t,n,jk]*trg[t,n,il]
// Outer product packed as 4 f32x2 pairs + 1 scalar per jk.
// ---------------------------------------------------------------------------
__global__ void reduce_kernel(const float* __restrict__ org,
                              const float* __restrict__ trg) {
    const int n    = blockIdx.y;
    const int base = blockIdx.x * blockDim.x + threadIdx.x;   // 0..2047

    u64   accP[9][4];
    float acc8[9];
#pragma unroll
    for (int j = 0; j < 9; j++) {
#pragma unroll
        for (int p = 0; p < 4; p++) accP[j][p] = 0ull;  // (+0.0f,+0.0f)
        acc8[j] = 0.0f;
    }

#pragma unroll
    for (int kk = 0; kk < 8; kk++) {
        const int t = base + kk * 2048;
        const float* a = org + (size_t)t * ROWLEN + n * 9;
        const float* b = trg + (size_t)t * ROWLEN + n * 9;
        float av[9], bv[9];
#pragma unroll
        for (int i = 0; i < 9; i++) { av[i] = a[i]; bv[i] = b[i]; }
        u64 bp[4];
#pragma unroll
        for (int p = 0; p < 4; p++) bp[p] = pk2(bv[2 * p], bv[2 * p + 1]);
#pragma unroll
        for (int j = 0; j < 9; j++) {
            u64 ad = pk2(av[j], av[j]);
#pragma unroll
            for (int p = 0; p < 4; p++) accP[j][p] = fma2(ad, bp[p], accP[j][p]);
            acc8[j] = fmaf(av[j], bv[8], acc8[j]);
        }
    }

    // unpack to 81 scalars, warp tree, cross-warp via smem
    float acc[81];
#pragma unroll
    for (int j = 0; j < 9; j++) {
#pragma unroll
        for (int p = 0; p < 4; p++)
            upk2(acc[j * 9 + 2 * p], acc[j * 9 + 2 * p + 1], accP[j][p]);
        acc[j * 9 + 8] = acc8[j];
    }

    const int lane = threadIdx.x & 31;
    const int wid  = threadIdx.x >> 5;
    __shared__ float sW[8][81];
#pragma unroll
    for (int e = 0; e < 81; e++) {
        float p = acc[e];
        p += __shfl_xor_sync(0xFFFFFFFFu, p, 16);
        p += __shfl_xor_sync(0xFFFFFFFFu, p, 8);
        p += __shfl_xor_sync(0xFFFFFFFFu, p, 4);
        p += __shfl_xor_sync(0xFFFFFFFFu, p, 2);
        p += __shfl_xor_sync(0xFFFFFFFFu, p, 1);
        if (lane == 0) sW[wid][e] = p;
    }
    __syncthreads();
    if (threadIdx.x < 81) {
        float s = 0.0f;
#pragma unroll
        for (int w = 0; w < 8; w++) s += sW[w][threadIdx.x];
        gPart[n][blockIdx.x][threadIdx.x] = s;
    }
}

// ---------------------------------------------------------------------------
// Threefry2x32-20, key (0,1), partitionable path: bits = o0 ^ o1.
// ---------------------------------------------------------------------------
__device__ __forceinline__ uint32_t rotl32(uint32_t v, uint32_t d) {
    return (v << d) | (v >> (32u - d));
}

__device__ void threefry_01(uint32_t x0, uint32_t x1, uint32_t& o0, uint32_t& o1) {
    const uint32_t k0 = 0u, k1 = 1u;
    const uint32_t k2 = k0 ^ k1 ^ 0x1BD11BDAu;
    x0 += k0; x1 += k1;
    x0 += x1; x1 = rotl32(x1, 13); x1 ^= x0;
    x0 += x1; x1 = rotl32(x1, 15); x1 ^= x0;
    x0 += x1; x1 = rotl32(x1, 26); x1 ^= x0;
    x0 += x1; x1 = rotl32(x1,  6); x1 ^= x0;
    x0 += k1; x1 += k2 + 1u;
    x0 += x1; x1 = rotl32(x1, 17); x1 ^= x0;
    x0 += x1; x1 = rotl32(x1, 29); x1 ^= x0;
    x0 += x1; x1 = rotl32(x1, 16); x1 ^= x0;
    x0 += x1; x1 = rotl32(x1, 24); x1 ^= x0;
    x0 += k2; x1 += k0 + 2u;
    x0 += x1; x1 = rotl32(x1, 13); x1 ^= x0;
    x0 += x1; x1 = rotl32(x1, 15); x1 ^= x0;
    x0 += x1; x1 = rotl32(x1, 26); x1 ^= x0;
    x0 += x1; x1 = rotl32(x1,  6); x1 ^= x0;
    x0 += k0; x1 += k1 + 3u;
    x0 += x1; x1 = rotl32(x1, 17); x1 ^= x0;
    x0 += x1; x1 = rotl32(x1, 29); x1 ^= x0;
    x0 += x1; x1 = rotl32(x1, 16); x1 ^= x0;
    x0 += x1; x1 = rotl32(x1, 24); x1 ^= x0;
    x0 += k1; x1 += k2 + 4u;
    x0 += x1; x1 = rotl32(x1, 13); x1 ^= x0;
    x0 += x1; x1 = rotl32(x1, 15); x1 ^= x0;
    x0 += x1; x1 = rotl32(x1, 26); x1 ^= x0;
    x0 += x1; x1 = rotl32(x1,  6); x1 ^= x0;
    x0 += k2; x1 += k0 + 5u;
    o0 = x0; o1 = x1;
}

__device__ float ang_init(int f) {
    uint32_t o0, o1;
    threefry_01(0u, (uint32_t)f, o0, o1);
    uint32_t bits = o0 ^ o1;
    uint32_t fb = (bits >> 9) | 0x3F800000u;
    return __uint_as_float(fb) - 1.0f;
}

// ---------------------------------------------------------------------------
// Kernel 2: 450 Adam iterations, one thread per sensor.
// Only 10 functionals of C are needed:
//   tD = T:C,  w_a = W_a:C,  S_pq = SS_pq:C  (S = D+D^T, 6 unique)
// packed into 5 f32x2 coefficient streams. Then
//   v = S k, q2 = k.Sk, kw = k.w,
//   alpha = -s*tD + (c-si)*kw + (0.5s-oi)*q2,
//   g_a = k_a*alpha + si*w_a + oi*v_a   (lw factor folded into coeffs).
// ---------------------------------------------------------------------------
__global__ void __launch_bounds__(32, 1) adam_kernel(float* __restrict__ out) {
    const int n = threadIdx.x;

    // --- per-iteration uniform constants: c1 = lr_t/(1-0.9^t), ib2 = 1/(1-0.999^t)
    __shared__ float2 sTab[NITER];
    {
        const float l2_09  = -0.15200309344504997f;   // log2(0.9)
        const float l2_0999 = -0.0014434504088372195f; // log2(0.999)
        for (int t = threadIdx.x; t < NITER; t += 32) {
            float tf = (float)(t + 1);
            float p1 = f_ex2(tf * l2_09);
            float p2 = f_ex2(tf * l2_0999);
            float lr = (t < 150) ? 0.01f : ((t < 300) ? 0.009f : 0.0081f);
            sTab[t].x = lr * f_rcp(1.0f - p1);
            sTab[t].y = f_rcp(1.0f - p2);
        }
    }
    __syncwarp();

    if (n >= NSENS) return;

    double Md[81];
#pragma unroll
    for (int e = 0; e < 81; e++) {
        double s = 0.0;
#pragma unroll
        for (int b = 0; b < NBLK; b++) s += (double)gPart[n][b][e];
        Md[e] = s;
    }

    // Ms(p,k,q,l) = -2*lw * (M[p,k,q,l] + M[k,p,l,q])
#define MSF(p, k, q, l) \
    (-20.0f * (float)(Md[(3*(p)+(k))*9 + 3*(q)+(l)] + Md[(3*(k)+(p))*9 + 3*(l)+(q)]))

    // packed coefficient streams over j = 3k+l:
    // PA=(T,Wx)  PB=(Wy,Wz)  PC=(S00,S01)  PD=(S02,S11)  PE=(S12,S22)
    u64 PA[9], PB[9], PC[9], PD[9], PE[9];
#pragma unroll
    for (int k = 0; k < 3; k++)
#pragma unroll
        for (int l = 0; l < 3; l++) {
            int j = 3 * k + l;
            float T  = MSF(0,k,0,l) + MSF(1,k,1,l) + MSF(2,k,2,l);
            float Wx = MSF(2,k,1,l) - MSF(1,k,2,l);
            float Wy = MSF(0,k,2,l) - MSF(2,k,0,l);
            float Wz = MSF(1,k,0,l) - MSF(0,k,1,l);
            float S00 = 2.0f * MSF(0,k,0,l);
            float S11 = 2.0f * MSF(1,k,1,l);
            float S22 = 2.0f * MSF(2,k,2,l);
            float S01 = MSF(0,k,1,l) + MSF(1,k,0,l);
            float S02 = MSF(0,k,2,l) + MSF(2,k,0,l);
            float S12 = MSF(1,k,2,l) + MSF(2,k,1,l);
            PA[j] = pk2(T,  Wx);
            PB[j] = pk2(Wy, Wz);
            PC[j] = pk2(S00, S01);
            PD[j] = pk2(S02, S11);
            PE[j] = pk2(S12, S22);
        }
#undef MSF

    float rx = ang_init(3 * n + 0);
    float ry = ang_init(3 * n + 1);
    float rz = ang_init(3 * n + 2);
    float mx = 0.f, my = 0.f, mz = 0.f;
    float vax = 0.f, vay = 0.f, vaz = 0.f;

#pragma unroll 1
    for (int it = 0; it < NITER; it++) {
        float2 tab = sTab[it];           // .x = lr/(1-b1^t), .y = 1/(1-b2^t)

        float th2 = fmaxf(fmaf(rx, rx, fmaf(ry, ry, rz * rz)), 1e-24f);
        float inv = f_rsqrt(th2);
        float th  = th2 * inv;
        float kx = rx * inv, ky = ry * inv, kz = rz * inv;
        float s = f_sin(th);
        float c = f_cos(th);
        float o = 1.0f - c;

        // C entries (row-major c0..c8), duplicated into packed regs
        float okx = o * kx, oky = o * ky, okz = o * kz;
        float skx = s * kx, sky = s * ky, skz = s * kz;
        float c0 = fmaf(okx, kx, c);
        float c1e = fmaf(okx, ky, -skz);
        float c2 = fmaf(okx, kz,  sky);
        float c3 = fmaf(oky, kx,  skz);
        float c4 = fmaf(oky, ky, c);
        float c5 = fmaf(oky, kz, -skx);
        float c6 = fmaf(okz, kx, -sky);
        float c7 = fmaf(okz, ky,  skx);
        float c8 = fmaf(okz, kz, c);
        u64 Cd[9];
        Cd[0] = pk2(c0, c0); Cd[1] = pk2(c1e, c1e); Cd[2] = pk2(c2, c2);
        Cd[3] = pk2(c3, c3); Cd[4] = pk2(c4, c4);  Cd[5] = pk2(c5, c5);
        Cd[6] = pk2(c6, c6); Cd[7] = pk2(c7, c7);  Cd[8] = pk2(c8, c8);

        // 5 packed contractions (9 steps each)
        u64 aA = mul2(PA[0], Cd[0]);
        u64 aB = mul2(PB[0], Cd[0]);
        u64 aC = mul2(PC[0], Cd[0]);
        u64 aD = mul2(PD[0], Cd[0]);
        u64 aE = mul2(PE[0], Cd[0]);
#pragma unroll
        for (int j = 1; j < 9; j++) {
            aA = fma2(PA[j], Cd[j], aA);
            aB = fma2(PB[j], Cd[j], aB);
            aC = fma2(PC[j], Cd[j], aC);
            aD = fma2(PD[j], Cd[j], aD);
            aE = fma2(PE[j], Cd[j], aE);
        }
        float tD, wx, wy, wz, S00, S01, S02, S11, S12, S22;
        upk2(tD,  wx,  aA);
        upk2(wy,  wz,  aB);
        upk2(S00, S01, aC);
        upk2(S02, S11, aD);
        upk2(S12, S22, aE);

        float vx = fmaf(S00, kx, fmaf(S01, ky, S02 * kz));
        float vy = fmaf(S01, kx, fmaf(S11, ky, S12 * kz));
        float vz = fmaf(S02, kx, fmaf(S12, ky, S22 * kz));
        float q2 = fmaf(kx, vx, fmaf(ky, vy, kz * vz));
        float kw = fmaf(kx, wx, fmaf(ky, wy, kz * wz));

        float si = s * inv;
        float oi = o * inv;
        float alpha = fmaf(-s, tD,
                      fmaf(c - si, kw, fmaf(0.5f, s, -oi) * q2));

        float gx = fmaf(kx, alpha, fmaf(si, wx, oi * vx));
        float gy = fmaf(ky, alpha, fmaf(si, wy, oi * vy));
        float gz = fmaf(kz, alpha, fmaf(si, wz, oi * vz));

        mx = fmaf(0.9f, mx, 0.1f * gx);
        my = fmaf(0.9f, my, 0.1f * gy);
        mz = fmaf(0.9f, mz, 0.1f * gz);
        vax = fmaf(0.999f, vax, 0.001f * gx * gx);
        vay = fmaf(0.999f, vay, 0.001f * gy * gy);
        vaz = fmaf(0.999f, vaz, 0.001f * gz * gz);

        // vhat >> eps^2 throughout (v has 1000-step memory, g_peak ~ O(1e3)),
        // so 1/(sqrt(vhat)+eps) == rsqrt(vhat) to ~1e-9 rel; +1e-30 guards inf.
        float rsx = f_rsqrt(fmaf(vax, tab.y, 1e-30f));
        float rsy = f_rsqrt(fmaf(vay, tab.y, 1e-30f));
        float rsz = f_rsqrt(fmaf(vaz, tab.y, 1e-30f));
        rx -= (tab.x * mx) * rsx;
        ry -= (tab.x * my) * rsy;
        rz -= (tab.x * mz) * rsz;
    }

    out[3 * n + 0] = rx;
    out[3 * n + 1] = ry;
    out[3 * n + 2] = rz;
}

// ---------------------------------------------------------------------------
extern "C" void kernel_launch(void* const* d_in, const int* in_sizes, int n_in,
                              void* d_out, int out_size) {
    const float* org = (const float*)d_in[0];
    const float* trg = (const float*)d_in[1];
    float* out = (float*)d_out;

    reduce_kernel<<<dim3(NBLK, NSENS), 256>>>(org, trg);
    adam_kernel<<<1, 32>>>(out);
}